// round 13
// baseline (speedup 1.0000x reference)
#include <cuda_runtime.h>
#include <math_constants.h>

#define RES      8
#define FEAT     512          // RES^3
#define NCLS     40
#define BMAX     64
#define BPB      16           // blocks per batch
#define NTHREADS 128
#define NWARPS   (NTHREADS / 32)

// ---------------- device scratch (no allocs allowed) ----------------
__device__ float g_mmP[BMAX * BPB * 6];    // per-block minmax partials
__device__ int   g_hist[BMAX * FEAT];
__device__ unsigned          g_barCount = 0;
__device__ volatile unsigned g_barGen   = 0;

// ---------------- software grid barrier (self-resetting, replay-safe) ----
__device__ __forceinline__ void gridBarrier(int nblocks) {
    __syncthreads();
    if (threadIdx.x == 0) {
        unsigned gen = g_barGen;
        __threadfence();                       // make my stores visible
        unsigned t = atomicAdd(&g_barCount, 1u);
        if (t == (unsigned)nblocks - 1u) {
            g_barCount = 0;                    // reset for next barrier/replay
            __threadfence();
            g_barGen = gen + 1u;               // release
        } else {
            while (g_barGen == gen) { __nanosleep(32); }
            __threadfence();                   // acquire
        }
    }
    __syncthreads();
}

__device__ __forceinline__ int bin_of(float p, float mn, float sc) {
    int i = (int)floorf((p - mn) * sc);
    return min(max(i, 0), RES - 1);
}

// ---------------- fused kernel ----------------
__global__ __launch_bounds__(NTHREADS, 8) void fused_kernel(
    const float* __restrict__ x, const float* __restrict__ W,
    const float* __restrict__ bias, float* __restrict__ out,
    int N, int B, int nblocks)
{
    __shared__ float red[NWARPS][6];
    __shared__ float s_mm[6];
    __shared__ int   sh[NWARPS][FEAT];     // per-warp privatized histograms (8 KB)

    const int b  = blockIdx.x / BPB;
    const int bb = blockIdx.x % BPB;
    const int tid  = threadIdx.x;
    const int warp = tid >> 5, lane = tid & 31;

    const float4* base = (const float4*)(x + (size_t)b * N * 3);
    const int ngroups = N >> 2;
    const int per = (ngroups + BPB - 1) / BPB;
    const int g0 = bb * per;
    const int g1 = min(g0 + per, ngroups);

    // ===================== Phase A: min/max (+ zero hist, warm W) =====================
    float mn0 =  CUDART_INF_F, mn1 =  CUDART_INF_F, mn2 =  CUDART_INF_F;
    float mx0 = -CUDART_INF_F, mx1 = -CUDART_INF_F, mx2 = -CUDART_INF_F;

    int g = g0 + tid;
    for (; g + NTHREADS < g1; g += 2 * NTHREADS) {
        float4 a0 = base[3 * g + 0];
        float4 v0 = base[3 * g + 1];
        float4 c0 = base[3 * g + 2];
        int h = g + NTHREADS;
        float4 a1 = base[3 * h + 0];
        float4 v1 = base[3 * h + 1];
        float4 c1 = base[3 * h + 2];
        // group 0: p0=(a.x,a.y,a.z) p1=(a.w,v.x,v.y) p2=(v.z,v.w,c.x) p3=(c.y,c.z,c.w)
        mn0 = fminf(mn0, fminf(fminf(a0.x, a0.w), fminf(v0.z, c0.y)));
        mx0 = fmaxf(mx0, fmaxf(fmaxf(a0.x, a0.w), fmaxf(v0.z, c0.y)));
        mn1 = fminf(mn1, fminf(fminf(a0.y, v0.x), fminf(v0.w, c0.z)));
        mx1 = fmaxf(mx1, fmaxf(fmaxf(a0.y, v0.x), fmaxf(v0.w, c0.z)));
        mn2 = fminf(mn2, fminf(fminf(a0.z, v0.y), fminf(c0.x, c0.w)));
        mx2 = fmaxf(mx2, fmaxf(fmaxf(a0.z, v0.y), fmaxf(c0.x, c0.w)));
        // group 1
        mn0 = fminf(mn0, fminf(fminf(a1.x, a1.w), fminf(v1.z, c1.y)));
        mx0 = fmaxf(mx0, fmaxf(fmaxf(a1.x, a1.w), fmaxf(v1.z, c1.y)));
        mn1 = fminf(mn1, fminf(fminf(a1.y, v1.x), fminf(v1.w, c1.z)));
        mx1 = fmaxf(mx1, fmaxf(fmaxf(a1.y, v1.x), fmaxf(v1.w, c1.z)));
        mn2 = fminf(mn2, fminf(fminf(a1.z, v1.y), fminf(c1.x, c1.w)));
        mx2 = fmaxf(mx2, fmaxf(fmaxf(a1.z, v1.y), fmaxf(c1.x, c1.w)));
    }
    for (; g < g1; g += NTHREADS) {
        float4 a = base[3 * g + 0];
        float4 v = base[3 * g + 1];
        float4 c = base[3 * g + 2];
        mn0 = fminf(mn0, fminf(fminf(a.x, a.w), fminf(v.z, c.y)));
        mx0 = fmaxf(mx0, fmaxf(fmaxf(a.x, a.w), fmaxf(v.z, c.y)));
        mn1 = fminf(mn1, fminf(fminf(a.y, v.x), fminf(v.w, c.z)));
        mx1 = fmaxf(mx1, fmaxf(fmaxf(a.y, v.x), fmaxf(v.w, c.z)));
        mn2 = fminf(mn2, fminf(fminf(a.z, v.y), fminf(c.x, c.w)));
        mx2 = fmaxf(mx2, fmaxf(fmaxf(a.z, v.y), fmaxf(c.x, c.w)));
    }
    // tail points (N % 4) handled by block bb==0
    int tail = N & 3;
    if (bb == 0 && tid < tail) {
        int n = (ngroups << 2) + tid;
        const float* p = x + ((size_t)b * N + n) * 3;
        mn0 = fminf(mn0, p[0]); mx0 = fmaxf(mx0, p[0]);
        mn1 = fminf(mn1, p[1]); mx1 = fmaxf(mx1, p[1]);
        mn2 = fminf(mn2, p[2]); mx2 = fmaxf(mx2, p[2]);
    }

    // zero this batch's hist row (bb==0 blocks) — before barrier
    if (bb == 0)
        for (int i = tid; i < FEAT; i += NTHREADS) g_hist[b * FEAT + i] = 0;

    // warm W into L2 for phase C: 1024 blocks x 5 float4 = all of W (5120 float4)
    if (tid < 5) {
        int wi = blockIdx.x * 5 + tid;
        if (wi < NCLS * FEAT / 4) {
            float4 w4 = ((const float4*)W)[wi];
            asm volatile("" :: "f"(w4.x), "f"(w4.y), "f"(w4.z), "f"(w4.w));
        }
    }

    // block-reduce min/max
    #pragma unroll
    for (int off = 16; off > 0; off >>= 1) {
        mn0 = fminf(mn0, __shfl_xor_sync(0xffffffffu, mn0, off));
        mn1 = fminf(mn1, __shfl_xor_sync(0xffffffffu, mn1, off));
        mn2 = fminf(mn2, __shfl_xor_sync(0xffffffffu, mn2, off));
        mx0 = fmaxf(mx0, __shfl_xor_sync(0xffffffffu, mx0, off));
        mx1 = fmaxf(mx1, __shfl_xor_sync(0xffffffffu, mx1, off));
        mx2 = fmaxf(mx2, __shfl_xor_sync(0xffffffffu, mx2, off));
    }
    if (lane == 0) {
        red[warp][0] = mn0; red[warp][1] = mn1; red[warp][2] = mn2;
        red[warp][3] = mx0; red[warp][4] = mx1; red[warp][5] = mx2;
    }
    __syncthreads();
    if (warp == 0 && lane < 6) {
        float v = red[0][lane];
        #pragma unroll
        for (int w = 1; w < NWARPS; w++) {
            float o = red[w][lane];
            v = (lane < 3) ? fminf(v, o) : fmaxf(v, o);
        }
        g_mmP[blockIdx.x * 6 + lane] = v;      // plain store, no init needed
    }

    gridBarrier(nblocks);

    // ===================== Phase B: histogram (per-warp privatized) =====================
    if (tid < 6) {
        float v = g_mmP[(b * BPB) * 6 + tid];
        #pragma unroll
        for (int p = 1; p < BPB; p++) {
            float o = g_mmP[(b * BPB + p) * 6 + tid];
            v = (tid < 3) ? fminf(v, o) : fmaxf(v, o);
        }
        s_mm[tid] = v;
    }
    for (int i = tid; i < NWARPS * FEAT; i += NTHREADS) ((int*)sh)[i] = 0;
    __syncthreads();

    const float mnx = s_mm[0], mny = s_mm[1], mnz = s_mm[2];
    float r0 = s_mm[3] - mnx, r1 = s_mm[4] - mny, r2 = s_mm[5] - mnz;
    const float sc0 = (float)RES / (r0 > 0.f ? r0 : 1.0f);
    const float sc1 = (float)RES / (r1 > 0.f ? r1 : 1.0f);
    const float sc2 = (float)RES / (r2 > 0.f ? r2 : 1.0f);

    int* hp = sh[warp];                      // this warp's private histogram
    g = g0 + tid;
    for (; g + NTHREADS < g1; g += 2 * NTHREADS) {
        float4 a0 = base[3 * g + 0];
        float4 v0 = base[3 * g + 1];
        float4 c0 = base[3 * g + 2];
        int h = g + NTHREADS;
        float4 a1 = base[3 * h + 0];
        float4 v1 = base[3 * h + 1];
        float4 c1 = base[3 * h + 2];
        int b0 = (bin_of(a0.x, mnx, sc0) * RES + bin_of(a0.y, mny, sc1)) * RES + bin_of(a0.z, mnz, sc2);
        int b1 = (bin_of(a0.w, mnx, sc0) * RES + bin_of(v0.x, mny, sc1)) * RES + bin_of(v0.y, mnz, sc2);
        int b2 = (bin_of(v0.z, mnx, sc0) * RES + bin_of(v0.w, mny, sc1)) * RES + bin_of(c0.x, mnz, sc2);
        int b3 = (bin_of(c0.y, mnx, sc0) * RES + bin_of(c0.z, mny, sc1)) * RES + bin_of(c0.w, mnz, sc2);
        int b4 = (bin_of(a1.x, mnx, sc0) * RES + bin_of(a1.y, mny, sc1)) * RES + bin_of(a1.z, mnz, sc2);
        int b5 = (bin_of(a1.w, mnx, sc0) * RES + bin_of(v1.x, mny, sc1)) * RES + bin_of(v1.y, mnz, sc2);
        int b6 = (bin_of(v1.z, mnx, sc0) * RES + bin_of(v1.w, mny, sc1)) * RES + bin_of(c1.x, mnz, sc2);
        int b7 = (bin_of(c1.y, mnx, sc0) * RES + bin_of(c1.z, mny, sc1)) * RES + bin_of(c1.w, mnz, sc2);
        atomicAdd(&hp[b0], 1);
        atomicAdd(&hp[b1], 1);
        atomicAdd(&hp[b2], 1);
        atomicAdd(&hp[b3], 1);
        atomicAdd(&hp[b4], 1);
        atomicAdd(&hp[b5], 1);
        atomicAdd(&hp[b6], 1);
        atomicAdd(&hp[b7], 1);
    }
    for (; g < g1; g += NTHREADS) {
        float4 a = base[3 * g + 0];
        float4 v = base[3 * g + 1];
        float4 c = base[3 * g + 2];
        int b0 = (bin_of(a.x, mnx, sc0) * RES + bin_of(a.y, mny, sc1)) * RES + bin_of(a.z, mnz, sc2);
        int b1 = (bin_of(a.w, mnx, sc0) * RES + bin_of(v.x, mny, sc1)) * RES + bin_of(v.y, mnz, sc2);
        int b2 = (bin_of(v.z, mnx, sc0) * RES + bin_of(v.w, mny, sc1)) * RES + bin_of(c.x, mnz, sc2);
        int b3 = (bin_of(c.y, mnx, sc0) * RES + bin_of(c.z, mny, sc1)) * RES + bin_of(c.w, mnz, sc2);
        atomicAdd(&hp[b0], 1);
        atomicAdd(&hp[b1], 1);
        atomicAdd(&hp[b2], 1);
        atomicAdd(&hp[b3], 1);
    }
    if (bb == 0 && tid < tail) {
        int n = (ngroups << 2) + tid;
        const float* p = x + ((size_t)b * N + n) * 3;
        int bn = (bin_of(p[0], mnx, sc0) * RES + bin_of(p[1], mny, sc1)) * RES + bin_of(p[2], mnz, sc2);
        atomicAdd(&hp[bn], 1);
    }
    __syncthreads();
    for (int i = tid; i < FEAT; i += NTHREADS) {
        int v = 0;
        #pragma unroll
        for (int w = 0; w < NWARPS; w++) v += sh[w][i];
        if (v) atomicAdd(&g_hist[b * FEAT + i], v);
    }

    gridBarrier(nblocks);

    // ===================== Phase C: linear, warp per (batch, class) =====================
    int wid = blockIdx.x * NWARPS + warp;   // 4096 warps, need B*NCLS = 2560
    if (wid < B * NCLS) {
        int ob = wid / NCLS;
        int c  = wid - ob * NCLS;
        const float4* wr = (const float4*)(W + (size_t)c * FEAT);
        const int4*   hr = (const int4*)(g_hist + ob * FEAT);
        float s = 0.f;
        #pragma unroll
        for (int i = 0; i < FEAT / 4 / 32; i++) {    // 4 iterations
            int idx = lane + 32 * i;
            float4 w4 = wr[idx];
            int4   h4 = hr[idx];
            s += w4.x * (float)h4.x;
            s += w4.y * (float)h4.y;
            s += w4.z * (float)h4.z;
            s += w4.w * (float)h4.w;
        }
        #pragma unroll
        for (int off = 16; off > 0; off >>= 1)
            s += __shfl_xor_sync(0xffffffffu, s, off);
        if (lane == 0)
            out[wid] = s * (1.0f / (float)N) + bias[c];
    }
}

// ---------------- launch ----------------
extern "C" void kernel_launch(void* const* d_in, const int* in_sizes, int n_in,
                              void* d_out, int out_size)
{
    const float* x    = (const float*)d_in[0];
    const float* W    = (const float*)d_in[1];
    const float* bias = (const float*)d_in[2];
    float* out = (float*)d_out;

    int B = out_size / NCLS;              // 64
    if (B > BMAX) B = BMAX;
    int N = in_sizes[0] / (3 * B);        // 100000

    int nblocks = B * BPB;                // 1024 — all resident (148 SMs x 8 = 1184 slots)
    fused_kernel<<<nblocks, NTHREADS>>>(x, W, bias, out, N, B, nblocks);
}

// round 15
// speedup vs baseline: 1.5019x; 1.5019x over previous
#include <cuda_runtime.h>
#include <math_constants.h>

#define RES      8
#define FEAT     512          // RES^3
#define NCLS     40
#define BMAX     64
#define BPB      16           // blocks per batch
#define NTHREADS 128
#define NWARPS   (NTHREADS / 32)

// ---------------- device scratch (no allocs allowed) ----------------
__device__ float g_mmP[BMAX * BPB * 6];    // per-block minmax partials
__device__ int   g_hist[BMAX * FEAT];
__device__ unsigned          g_barCount = 0;
__device__ volatile unsigned g_barGen   = 0;

// ---------------- software grid barrier (self-resetting, replay-safe) ----
__device__ __forceinline__ void gridBarrier(int nblocks) {
    __syncthreads();
    if (threadIdx.x == 0) {
        unsigned gen = g_barGen;
        __threadfence();                       // make my stores visible
        unsigned t = atomicAdd(&g_barCount, 1u);
        if (t == (unsigned)nblocks - 1u) {
            g_barCount = 0;                    // reset for next barrier/replay
            __threadfence();
            g_barGen = gen + 1u;               // release
        } else {
            while (g_barGen == gen) { __nanosleep(32); }
            __threadfence();                   // acquire
        }
    }
    __syncthreads();
}

__device__ __forceinline__ int bin_of(float p, float mn, float sc) {
    int i = (int)floorf((p - mn) * sc);
    return min(max(i, 0), RES - 1);
}

// ---------------- fused kernel ----------------
__global__ __launch_bounds__(NTHREADS, 10) void fused_kernel(
    const float* __restrict__ x, const float* __restrict__ W,
    const float* __restrict__ bias, float* __restrict__ out,
    int N, int B, int nblocks)
{
    __shared__ float red[NWARPS][6];
    __shared__ float s_mm[6];
    __shared__ int   sh[NWARPS][FEAT];     // per-warp privatized histograms (8 KB)

    const int b  = blockIdx.x / BPB;
    const int bb = blockIdx.x % BPB;
    const int tid  = threadIdx.x;
    const int warp = tid >> 5, lane = tid & 31;

    const float4* base = (const float4*)(x + (size_t)b * N * 3);
    const int ngroups = N >> 2;
    const int per = (ngroups + BPB - 1) / BPB;
    const int g0 = bb * per;
    const int g1 = min(g0 + per, ngroups);

    // ===================== Phase A: min/max (+ zero hist, warm W) =====================
    float mn0 =  CUDART_INF_F, mn1 =  CUDART_INF_F, mn2 =  CUDART_INF_F;
    float mx0 = -CUDART_INF_F, mx1 = -CUDART_INF_F, mx2 = -CUDART_INF_F;

    for (int g = g0 + tid; g < g1; g += NTHREADS) {
        float4 a = base[3 * g + 0];
        float4 v = base[3 * g + 1];
        float4 c = base[3 * g + 2];
        // p0=(a.x,a.y,a.z) p1=(a.w,v.x,v.y) p2=(v.z,v.w,c.x) p3=(c.y,c.z,c.w)
        mn0 = fminf(mn0, fminf(fminf(a.x, a.w), fminf(v.z, c.y)));
        mx0 = fmaxf(mx0, fmaxf(fmaxf(a.x, a.w), fmaxf(v.z, c.y)));
        mn1 = fminf(mn1, fminf(fminf(a.y, v.x), fminf(v.w, c.z)));
        mx1 = fmaxf(mx1, fmaxf(fmaxf(a.y, v.x), fmaxf(v.w, c.z)));
        mn2 = fminf(mn2, fminf(fminf(a.z, v.y), fminf(c.x, c.w)));
        mx2 = fmaxf(mx2, fmaxf(fmaxf(a.z, v.y), fmaxf(c.x, c.w)));
    }
    // tail points (N % 4) handled by block bb==0
    int tail = N & 3;
    if (bb == 0 && tid < tail) {
        int n = (ngroups << 2) + tid;
        const float* p = x + ((size_t)b * N + n) * 3;
        mn0 = fminf(mn0, p[0]); mx0 = fmaxf(mx0, p[0]);
        mn1 = fminf(mn1, p[1]); mx1 = fmaxf(mx1, p[1]);
        mn2 = fminf(mn2, p[2]); mx2 = fmaxf(mx2, p[2]);
    }

    // zero this batch's hist row (bb==0 blocks) — before barrier
    if (bb == 0)
        for (int i = tid; i < FEAT; i += NTHREADS) g_hist[b * FEAT + i] = 0;

    // warm W into L2 for phase C: 1024 blocks x 5 float4 = all of W (5120 float4)
    if (tid < 5) {
        int wi = blockIdx.x * 5 + tid;
        if (wi < NCLS * FEAT / 4) {
            float4 w4 = ((const float4*)W)[wi];
            asm volatile("" :: "f"(w4.x), "f"(w4.y), "f"(w4.z), "f"(w4.w));
        }
    }

    // block-reduce min/max
    #pragma unroll
    for (int off = 16; off > 0; off >>= 1) {
        mn0 = fminf(mn0, __shfl_xor_sync(0xffffffffu, mn0, off));
        mn1 = fminf(mn1, __shfl_xor_sync(0xffffffffu, mn1, off));
        mn2 = fminf(mn2, __shfl_xor_sync(0xffffffffu, mn2, off));
        mx0 = fmaxf(mx0, __shfl_xor_sync(0xffffffffu, mx0, off));
        mx1 = fmaxf(mx1, __shfl_xor_sync(0xffffffffu, mx1, off));
        mx2 = fmaxf(mx2, __shfl_xor_sync(0xffffffffu, mx2, off));
    }
    if (lane == 0) {
        red[warp][0] = mn0; red[warp][1] = mn1; red[warp][2] = mn2;
        red[warp][3] = mx0; red[warp][4] = mx1; red[warp][5] = mx2;
    }
    __syncthreads();
    if (warp == 0 && lane < 6) {
        float v = red[0][lane];
        #pragma unroll
        for (int w = 1; w < NWARPS; w++) {
            float o = red[w][lane];
            v = (lane < 3) ? fminf(v, o) : fmaxf(v, o);
        }
        g_mmP[blockIdx.x * 6 + lane] = v;      // plain store, no init needed
    }

    gridBarrier(nblocks);

    // ===================== Phase B: histogram (per-warp privatized) =====================
    if (tid < 6) {
        float v = g_mmP[(b * BPB) * 6 + tid];
        #pragma unroll
        for (int p = 1; p < BPB; p++) {
            float o = g_mmP[(b * BPB + p) * 6 + tid];
            v = (tid < 3) ? fminf(v, o) : fmaxf(v, o);
        }
        s_mm[tid] = v;
    }
    for (int i = tid; i < NWARPS * FEAT; i += NTHREADS) ((int*)sh)[i] = 0;
    __syncthreads();

    const float mnx = s_mm[0], mny = s_mm[1], mnz = s_mm[2];
    float r0 = s_mm[3] - mnx, r1 = s_mm[4] - mny, r2 = s_mm[5] - mnz;
    const float sc0 = (float)RES / (r0 > 0.f ? r0 : 1.0f);
    const float sc1 = (float)RES / (r1 > 0.f ? r1 : 1.0f);
    const float sc2 = (float)RES / (r2 > 0.f ? r2 : 1.0f);

    int* hp = sh[warp];                      // this warp's private histogram
    for (int g = g0 + tid; g < g1; g += NTHREADS) {
        float4 a = base[3 * g + 0];
        float4 v = base[3 * g + 1];
        float4 c = base[3 * g + 2];
        int b0 = (bin_of(a.x, mnx, sc0) * RES + bin_of(a.y, mny, sc1)) * RES + bin_of(a.z, mnz, sc2);
        int b1 = (bin_of(a.w, mnx, sc0) * RES + bin_of(v.x, mny, sc1)) * RES + bin_of(v.y, mnz, sc2);
        int b2 = (bin_of(v.z, mnx, sc0) * RES + bin_of(v.w, mny, sc1)) * RES + bin_of(c.x, mnz, sc2);
        int b3 = (bin_of(c.y, mnx, sc0) * RES + bin_of(c.z, mny, sc1)) * RES + bin_of(c.w, mnz, sc2);
        atomicAdd(&hp[b0], 1);
        atomicAdd(&hp[b1], 1);
        atomicAdd(&hp[b2], 1);
        atomicAdd(&hp[b3], 1);
    }
    if (bb == 0 && tid < tail) {
        int n = (ngroups << 2) + tid;
        const float* p = x + ((size_t)b * N + n) * 3;
        int bn = (bin_of(p[0], mnx, sc0) * RES + bin_of(p[1], mny, sc1)) * RES + bin_of(p[2], mnz, sc2);
        atomicAdd(&hp[bn], 1);
    }
    __syncthreads();
    for (int i = tid; i < FEAT; i += NTHREADS) {
        int v = 0;
        #pragma unroll
        for (int w = 0; w < NWARPS; w++) v += sh[w][i];
        if (v) atomicAdd(&g_hist[b * FEAT + i], v);
    }

    gridBarrier(nblocks);

    // ===================== Phase C: linear, warp per (batch, class) =====================
    int wid = blockIdx.x * NWARPS + warp;   // 4096 warps, need B*NCLS = 2560
    if (wid < B * NCLS) {
        int ob = wid / NCLS;
        int c  = wid - ob * NCLS;
        const float4* wr = (const float4*)(W + (size_t)c * FEAT);
        const int4*   hr = (const int4*)(g_hist + ob * FEAT);
        float s = 0.f;
        #pragma unroll
        for (int i = 0; i < FEAT / 4 / 32; i++) {    // 4 iterations
            int idx = lane + 32 * i;
            float4 w4 = wr[idx];
            int4   h4 = hr[idx];
            s += w4.x * (float)h4.x;
            s += w4.y * (float)h4.y;
            s += w4.z * (float)h4.z;
            s += w4.w * (float)h4.w;
        }
        #pragma unroll
        for (int off = 16; off > 0; off >>= 1)
            s += __shfl_xor_sync(0xffffffffu, s, off);
        if (lane == 0)
            out[wid] = s * (1.0f / (float)N) + bias[c];
    }
}

// ---------------- launch ----------------
extern "C" void kernel_launch(void* const* d_in, const int* in_sizes, int n_in,
                              void* d_out, int out_size)
{
    const float* x    = (const float*)d_in[0];
    const float* W    = (const float*)d_in[1];
    const float* bias = (const float*)d_in[2];
    float* out = (float*)d_out;

    int B = out_size / NCLS;              // 64
    if (B > BMAX) B = BMAX;
    int N = in_sizes[0] / (3 * B);        // 100000

    int nblocks = B * BPB;                // 1024 — all resident (148 SMs x 10 = 1480 slots)
    fused_kernel<<<nblocks, NTHREADS>>>(x, W, bias, out, N, B, nblocks);
}